// round 1
// baseline (speedup 1.0000x reference)
#include <cuda_runtime.h>
#include <cuda_bf16.h>
#include <math.h>

// Problem constants
#define SEQ    4096
#define DIN    1024
#define DOUT   1024
#define NHEAD  16
#define HD     64          // head dim
#define SCALE  0.125f      // 1/sqrt(64)

// ---------------- scratch (allocation-free: __device__ globals) -------------
__device__ float g_Q[SEQ * DOUT];
__device__ float g_K[SEQ * DOUT];
__device__ float g_V[SEQ * DOUT];
__device__ float g_A[SEQ * DOUT];   // attention output (pre Wo)

// ---------------- SGEMM: C[M,N] = A[M,K] * B[K,N], fp32 ---------------------
// 128x128 block tile, 8 K-slice, 256 threads, 8x8 per-thread register tile.
#define BM 128
#define BN 128
#define BKK 8

__device__ __forceinline__ void sgemm_body(const float* __restrict__ A,
                                           const float* __restrict__ B,
                                           float* __restrict__ C,
                                           int M, int N, int K,
                                           int bm, int bn)
{
    __shared__ float As[BKK][BM];      // transposed A tile
    __shared__ float Bs[BKK][BN];

    const int tid = threadIdx.x;           // 0..255
    const int tr  = tid >> 4;              // 0..15  (row group)
    const int tc  = tid & 15;              // 0..15  (col group)

    // global-load mapping
    const int arow = tid >> 1;              // 0..127
    const int acol = (tid & 1) * 4;         // 0 or 4
    const int brow = tid >> 5;              // 0..7
    const int bcol = (tid & 31) * 4;        // 0..124

    const float* Ab = A + (size_t)(bm * BM) * K;
    const float* Bb = B + bn * BN;

    float acc[8][8];
#pragma unroll
    for (int i = 0; i < 8; i++)
#pragma unroll
        for (int j = 0; j < 8; j++) acc[i][j] = 0.f;

    for (int k0 = 0; k0 < K; k0 += BKK) {
        float4 a4 = *(const float4*)(Ab + (size_t)arow * K + k0 + acol);
        float4 b4 = *(const float4*)(Bb + (size_t)(k0 + brow) * N + bcol);
        As[acol + 0][arow] = a4.x;
        As[acol + 1][arow] = a4.y;
        As[acol + 2][arow] = a4.z;
        As[acol + 3][arow] = a4.w;
        *(float4*)&Bs[brow][bcol] = b4;
        __syncthreads();

#pragma unroll
        for (int k = 0; k < BKK; k++) {
            float ar[8], br[8];
            float4 t;
            t = *(const float4*)&As[k][tr * 8 + 0]; ar[0]=t.x; ar[1]=t.y; ar[2]=t.z; ar[3]=t.w;
            t = *(const float4*)&As[k][tr * 8 + 4]; ar[4]=t.x; ar[5]=t.y; ar[6]=t.z; ar[7]=t.w;
            t = *(const float4*)&Bs[k][tc * 8 + 0]; br[0]=t.x; br[1]=t.y; br[2]=t.z; br[3]=t.w;
            t = *(const float4*)&Bs[k][tc * 8 + 4]; br[4]=t.x; br[5]=t.y; br[6]=t.z; br[7]=t.w;
#pragma unroll
            for (int i = 0; i < 8; i++)
#pragma unroll
                for (int j = 0; j < 8; j++)
                    acc[i][j] = fmaf(ar[i], br[j], acc[i][j]);
        }
        __syncthreads();
    }

    float* Cb = C + (size_t)(bm * BM + tr * 8) * N + bn * BN + tc * 8;
#pragma unroll
    for (int i = 0; i < 8; i++) {
        float4 v0 = make_float4(acc[i][0], acc[i][1], acc[i][2], acc[i][3]);
        float4 v1 = make_float4(acc[i][4], acc[i][5], acc[i][6], acc[i][7]);
        *(float4*)(Cb + (size_t)i * N + 0) = v0;
        *(float4*)(Cb + (size_t)i * N + 4) = v1;
    }
}

// QKV fused: blockIdx.z selects (Wq->g_Q), (Wk->g_K), (Wv->g_V)
__global__ __launch_bounds__(256)
void sgemm_qkv_kernel(const float* __restrict__ X,
                      const float* __restrict__ Wq,
                      const float* __restrict__ Wk,
                      const float* __restrict__ Wv)
{
    const float* B = (blockIdx.z == 0) ? Wq : (blockIdx.z == 1) ? Wk : Wv;
    float* C = (blockIdx.z == 0) ? g_Q : (blockIdx.z == 1) ? g_K : g_V;
    sgemm_body(X, B, C, SEQ, DOUT, DIN, blockIdx.y, blockIdx.x);
}

// Output projection: d_out = g_A @ Wo
__global__ __launch_bounds__(256)
void sgemm_out_kernel(const float* __restrict__ Wo, float* __restrict__ out)
{
    sgemm_body(g_A, Wo, out, SEQ, DOUT, DOUT, blockIdx.y, blockIdx.x);
}

// ---------------- Flash attention (fp32, causal) ----------------------------
// One block = (head h, 128 query rows). 128 threads, one query row per thread.
// q row + O accumulator in registers; K/V tiles in SMEM read via broadcast.
#define BQ  128
#define BKV 64
#define JCH 16      // score chunk size

__global__ __launch_bounds__(128)
void attn_kernel()
{
    const int h  = blockIdx.y;
    const int q0 = blockIdx.x * BQ;
    const int tid = threadIdx.x;
    const int r  = q0 + tid;                 // this thread's query row

    __shared__ float Ks[BKV][HD];
    __shared__ float Vs[BKV][HD];

    // load q row into registers
    float q[HD];
    const float* qptr = g_Q + (size_t)r * DOUT + h * HD;
#pragma unroll
    for (int d = 0; d < HD; d += 4) {
        float4 t = *(const float4*)(qptr + d);
        q[d] = t.x; q[d+1] = t.y; q[d+2] = t.z; q[d+3] = t.w;
    }

    float o[HD];
#pragma unroll
    for (int d = 0; d < HD; d++) o[d] = 0.f;
    float m = -1e30f, l = 0.f;

    const int kv_end = q0 + BQ;              // causal: keys <= last row of block

    for (int j0 = 0; j0 < kv_end; j0 += BKV) {
        // cooperative K/V tile load: 1024 float4 per tile, 128 threads -> 8 each
        const float* kb = g_K + (size_t)j0 * DOUT + h * HD;
        const float* vb = g_V + (size_t)j0 * DOUT + h * HD;
#pragma unroll
        for (int it = 0; it < (BKV * HD / 4) / 128; it++) {
            int i = tid + it * 128;               // float4 index
            int jr = i >> 4;                      // i / (HD/4)
            int d  = (i & 15) * 4;
            *(float4*)&Ks[jr][d] = *(const float4*)(kb + (size_t)jr * DOUT + d);
            *(float4*)&Vs[jr][d] = *(const float4*)(vb + (size_t)jr * DOUT + d);
        }
        __syncthreads();

#pragma unroll 1
        for (int jj0 = 0; jj0 < BKV; jj0 += JCH) {
            float s[JCH];
#pragma unroll
            for (int jj = 0; jj < JCH; jj++) s[jj] = 0.f;

#pragma unroll
            for (int d = 0; d < HD; d += 4) {
#pragma unroll
                for (int jj = 0; jj < JCH; jj++) {
                    float4 k4 = *(const float4*)&Ks[jj0 + jj][d];
                    s[jj] = fmaf(q[d+0], k4.x, s[jj]);
                    s[jj] = fmaf(q[d+1], k4.y, s[jj]);
                    s[jj] = fmaf(q[d+2], k4.z, s[jj]);
                    s[jj] = fmaf(q[d+3], k4.w, s[jj]);
                }
            }

            // scale + causal mask
            float cm = -1e30f;
#pragma unroll
            for (int jj = 0; jj < JCH; jj++) {
                int j = j0 + jj0 + jj;
                s[jj] = (j > r) ? -1e30f : s[jj] * SCALE;
                cm = fmaxf(cm, s[jj]);
            }

            float mnew  = fmaxf(m, cm);
            float alpha = __expf(m - mnew);
            l *= alpha;
#pragma unroll
            for (int d = 0; d < HD; d++) o[d] *= alpha;

#pragma unroll
            for (int jj = 0; jj < JCH; jj++) {
                float p = __expf(s[jj] - mnew);
                l += p;
#pragma unroll
                for (int d = 0; d < HD; d += 4) {
                    float4 v4 = *(const float4*)&Vs[jj0 + jj][d];
                    o[d+0] = fmaf(p, v4.x, o[d+0]);
                    o[d+1] = fmaf(p, v4.y, o[d+1]);
                    o[d+2] = fmaf(p, v4.z, o[d+2]);
                    o[d+3] = fmaf(p, v4.w, o[d+3]);
                }
            }
            m = mnew;
        }
        __syncthreads();
    }

    const float inv = 1.f / l;
    float* optr = g_A + (size_t)r * DOUT + h * HD;
#pragma unroll
    for (int d = 0; d < HD; d += 4) {
        float4 t = make_float4(o[d] * inv, o[d+1] * inv, o[d+2] * inv, o[d+3] * inv);
        *(float4*)(optr + d) = t;
    }
}

// ---------------- launch -----------------------------------------------------
extern "C" void kernel_launch(void* const* d_in, const int* in_sizes, int n_in,
                              void* d_out, int out_size)
{
    const float* x  = (const float*)d_in[0];
    const float* Wq = (const float*)d_in[1];
    const float* Wk = (const float*)d_in[2];
    const float* Wv = (const float*)d_in[3];
    const float* Wo = (const float*)d_in[4];
    float* out = (float*)d_out;

    dim3 gQKV(DOUT / BN, SEQ / BM, 3);
    sgemm_qkv_kernel<<<gQKV, 256>>>(x, Wq, Wk, Wv);

    dim3 gAtt(SEQ / BQ, NHEAD);
    attn_kernel<<<gAtt, 128>>>();

    dim3 gOut(DOUT / BN, SEQ / BM, 1);
    sgemm_out_kernel<<<gOut, 256>>>(Wo, out);
}

// round 2
// speedup vs baseline: 1.5711x; 1.5711x over previous
#include <cuda_runtime.h>
#include <cuda_bf16.h>
#include <math.h>
#include <stdint.h>

// Problem constants
#define SEQ    4096
#define DIN    1024
#define DOUT   1024
#define NHEAD  16
#define HD     64
#define SCALE  0.125f

// ---------------- scratch -----------------------------------------------------
__device__ float g_Q[SEQ * DOUT];
__device__ float g_K[SEQ * DOUT];
__device__ float g_V[SEQ * DOUT];
__device__ float g_A[SEQ * DOUT];

// ---------------- helpers ------------------------------------------------------
__device__ __forceinline__ uint32_t f2tf(float x) {
    uint32_t r;
    asm("cvt.rna.tf32.f32 %0, %1;" : "=r"(r) : "f"(x));
    return r;
}

__device__ __forceinline__ void mma8(float* c, const uint32_t* a, const uint32_t* b) {
    asm volatile(
        "mma.sync.aligned.m16n8k8.row.col.f32.tf32.tf32.f32 "
        "{%0,%1,%2,%3}, {%4,%5,%6,%7}, {%8,%9}, {%0,%1,%2,%3};"
        : "+f"(c[0]), "+f"(c[1]), "+f"(c[2]), "+f"(c[3])
        : "r"(a[0]), "r"(a[1]), "r"(a[2]), "r"(a[3]), "r"(b[0]), "r"(b[1]));
}

// ---------------- 3xTF32 GEMM: C[4096,1024] = A[4096,1024] x B[1024,1024] ------
// 128x128 block tile, BK=16, 256 threads (8 warps, 2x4), warp tile 64x32.
#define GAST 20     // A smem stride (16 + 4 pad)
#define GBST 136    // B smem stride (128 + 8 pad)

__device__ __forceinline__ void gemm3x_body(const float* __restrict__ A,
                                            const float* __restrict__ B,
                                            float* __restrict__ C,
                                            int bm, int bn)
{
    __shared__ uint32_t Ash[128][GAST];
    __shared__ uint32_t Asl[128][GAST];
    __shared__ uint32_t Bsh[16][GBST];
    __shared__ uint32_t Bsl[16][GBST];

    const int tid  = threadIdx.x;
    const int w    = tid >> 5;
    const int lane = tid & 31;
    const int g    = lane >> 2;
    const int t    = lane & 3;
    const int wm   = w >> 2;           // 0..1
    const int wn   = w & 3;            // 0..3

    const float* Ab = A + (size_t)(bm * 128) * 1024;
    const float* Bb = B + bn * 128;

    const int arow = tid >> 2;          // 0..63
    const int ac   = (tid & 3) * 4;     // 0,4,8,12
    const int brow = tid >> 5;          // 0..7
    const int bc   = (tid & 31) * 4;    // 0..124

    float acc[4][4][4];
#pragma unroll
    for (int i = 0; i < 4; i++)
#pragma unroll
        for (int j = 0; j < 4; j++)
#pragma unroll
            for (int e = 0; e < 4; e++) acc[i][j][e] = 0.f;

    float4 pa[2], pb[2];
#pragma unroll
    for (int i = 0; i < 2; i++) {
        pa[i] = *(const float4*)(Ab + (size_t)(arow + i * 64) * 1024 + ac);
        pb[i] = *(const float4*)(Bb + (size_t)(brow + i * 8) * 1024 + bc);
    }

    for (int kt = 0; kt < 64; kt++) {
        // split hi/lo and stage to smem
#pragma unroll
        for (int i = 0; i < 2; i++) {
            int r = arow + i * 64;
            float v[4] = {pa[i].x, pa[i].y, pa[i].z, pa[i].w};
#pragma unroll
            for (int e = 0; e < 4; e++) {
                uint32_t hi = f2tf(v[e]);
                Ash[r][ac + e] = hi;
                Asl[r][ac + e] = f2tf(v[e] - __uint_as_float(hi));
            }
            int rb = brow + i * 8;
            float u[4] = {pb[i].x, pb[i].y, pb[i].z, pb[i].w};
#pragma unroll
            for (int e = 0; e < 4; e++) {
                uint32_t hi = f2tf(u[e]);
                Bsh[rb][bc + e] = hi;
                Bsl[rb][bc + e] = f2tf(u[e] - __uint_as_float(hi));
            }
        }
        __syncthreads();

        if (kt < 63) {
            int k0 = (kt + 1) * 16;
#pragma unroll
            for (int i = 0; i < 2; i++) {
                pa[i] = *(const float4*)(Ab + (size_t)(arow + i * 64) * 1024 + k0 + ac);
                pb[i] = *(const float4*)(Bb + (size_t)(k0 + brow + i * 8) * 1024 + bc);
            }
        }

#pragma unroll
        for (int ks = 0; ks < 2; ks++) {
            uint32_t Ah[4][4], Al[4][4], Bh[4][2], Bl[4][2];
#pragma unroll
            for (int mt = 0; mt < 4; mt++) {
                int r0 = wm * 64 + mt * 16 + g;
                Ah[mt][0] = Ash[r0][ks * 8 + t];
                Ah[mt][1] = Ash[r0 + 8][ks * 8 + t];
                Ah[mt][2] = Ash[r0][ks * 8 + t + 4];
                Ah[mt][3] = Ash[r0 + 8][ks * 8 + t + 4];
                Al[mt][0] = Asl[r0][ks * 8 + t];
                Al[mt][1] = Asl[r0 + 8][ks * 8 + t];
                Al[mt][2] = Asl[r0][ks * 8 + t + 4];
                Al[mt][3] = Asl[r0 + 8][ks * 8 + t + 4];
            }
#pragma unroll
            for (int nt = 0; nt < 4; nt++) {
                int col = wn * 32 + nt * 8 + g;
                Bh[nt][0] = Bsh[ks * 8 + t][col];
                Bh[nt][1] = Bsh[ks * 8 + t + 4][col];
                Bl[nt][0] = Bsl[ks * 8 + t][col];
                Bl[nt][1] = Bsl[ks * 8 + t + 4][col];
            }
#pragma unroll
            for (int mt = 0; mt < 4; mt++)
#pragma unroll
                for (int nt = 0; nt < 4; nt++) {
                    mma8(acc[mt][nt], Ah[mt], Bh[nt]);
                    mma8(acc[mt][nt], Ah[mt], Bl[nt]);
                    mma8(acc[mt][nt], Al[mt], Bh[nt]);
                }
        }
        __syncthreads();
    }

    // epilogue
#pragma unroll
    for (int mt = 0; mt < 4; mt++) {
        int r0 = bm * 128 + wm * 64 + mt * 16 + g;
#pragma unroll
        for (int nt = 0; nt < 4; nt++) {
            int col = bn * 128 + wn * 32 + nt * 8 + 2 * t;
            *(float2*)(C + (size_t)r0 * 1024 + col)       = make_float2(acc[mt][nt][0], acc[mt][nt][1]);
            *(float2*)(C + (size_t)(r0 + 8) * 1024 + col) = make_float2(acc[mt][nt][2], acc[mt][nt][3]);
        }
    }
}

__global__ __launch_bounds__(256)
void gemm_qkv_kernel(const float* __restrict__ X,
                     const float* __restrict__ Wq,
                     const float* __restrict__ Wk,
                     const float* __restrict__ Wv)
{
    const float* B = (blockIdx.z == 0) ? Wq : (blockIdx.z == 1) ? Wk : Wv;
    float* C = (blockIdx.z == 0) ? g_Q : (blockIdx.z == 1) ? g_K : g_V;
    gemm3x_body(X, B, C, blockIdx.y, blockIdx.x);
}

__global__ __launch_bounds__(256)
void gemm_wo_kernel(const float* __restrict__ Wo, float* __restrict__ out)
{
    gemm3x_body(g_A, Wo, out, blockIdx.y, blockIdx.x);
}

// ---------------- Flash attention: tf32 mma, causal ---------------------------
// Block = (head, 64 query rows), 4 warps (16 rows each). KV tile = 32 keys.
// QK^T single tf32; PV 3xTF32 (P and V split).
#define KST 72   // K/V smem stride (64 + 8)

__global__ __launch_bounds__(128)
void attn_kernel()
{
    __shared__ uint32_t Ks[32][KST];
    __shared__ uint32_t Vh[32][KST];
    __shared__ uint32_t Vl[32][KST];

    const int h   = blockIdx.y;
    const int q0  = blockIdx.x * 64;
    const int tid = threadIdx.x;
    const int w   = tid >> 5;
    const int lane = tid & 31;
    const int g   = lane >> 2;
    const int t   = lane & 3;

    const int r0 = q0 + 16 * w + g;
    const int r1 = r0 + 8;

    // Q fragments (8 d-chunks), tf32
    uint32_t qf[8][4];
    {
        const float* Qb = g_Q + (size_t)0 * 0;  // base
#pragma unroll
        for (int kc = 0; kc < 8; kc++) {
            int col = h * HD + kc * 8;
            qf[kc][0] = f2tf(g_Q[(size_t)r0 * 1024 + col + t]);
            qf[kc][1] = f2tf(g_Q[(size_t)r1 * 1024 + col + t]);
            qf[kc][2] = f2tf(g_Q[(size_t)r0 * 1024 + col + t + 4]);
            qf[kc][3] = f2tf(g_Q[(size_t)r1 * 1024 + col + t + 4]);
        }
        (void)Qb;
    }

    float o[8][4];
#pragma unroll
    for (int nd = 0; nd < 8; nd++)
#pragma unroll
        for (int e = 0; e < 4; e++) o[nd][e] = 0.f;
    float m0 = -1e4f, m1 = -1e4f, l0 = 0.f, l1 = 0.f;

    const int ntiles = q0 / 32 + 2;

    for (int it = 0; it < ntiles; it++) {
        const int j0 = it * 32;
        const bool domask = (j0 >= q0);

        // cooperative K/V load + tf32 split
        const float* kb = g_K + (size_t)j0 * 1024 + h * HD;
        const float* vb = g_V + (size_t)j0 * 1024 + h * HD;
#pragma unroll
        for (int i = 0; i < 4; i++) {
            int idx = tid + i * 128;      // 0..511
            int row = idx >> 4;           // 0..31
            int c4  = (idx & 15) * 4;
            float4 kv = *(const float4*)(kb + (size_t)row * 1024 + c4);
            Ks[row][c4 + 0] = f2tf(kv.x);
            Ks[row][c4 + 1] = f2tf(kv.y);
            Ks[row][c4 + 2] = f2tf(kv.z);
            Ks[row][c4 + 3] = f2tf(kv.w);
            float4 vv = *(const float4*)(vb + (size_t)row * 1024 + c4);
            float vr[4] = {vv.x, vv.y, vv.z, vv.w};
#pragma unroll
            for (int e = 0; e < 4; e++) {
                uint32_t hi = f2tf(vr[e]);
                Vh[row][c4 + e] = hi;
                Vl[row][c4 + e] = f2tf(vr[e] - __uint_as_float(hi));
            }
        }
        __syncthreads();

        // S = Q K^T  (4 key-tiles of 8)
        float s[4][4];
#pragma unroll
        for (int nt = 0; nt < 4; nt++)
#pragma unroll
            for (int e = 0; e < 4; e++) s[nt][e] = 0.f;

#pragma unroll
        for (int kc = 0; kc < 8; kc++) {
#pragma unroll
            for (int nt = 0; nt < 4; nt++) {
                uint32_t b[2];
                b[0] = Ks[nt * 8 + g][kc * 8 + t];
                b[1] = Ks[nt * 8 + g][kc * 8 + t + 4];
                mma8(s[nt], qf[kc], b);
            }
        }

        // scale + mask + row max
        float mx0 = -1e30f, mx1 = -1e30f;
#pragma unroll
        for (int nt = 0; nt < 4; nt++) {
            int jc = j0 + nt * 8 + 2 * t;
#pragma unroll
            for (int e = 0; e < 4; e++) {
                int j = jc + (e & 1);
                int r = (e < 2) ? r0 : r1;
                float sc = s[nt][e] * SCALE;
                if (domask && j > r) sc = -1e30f;
                s[nt][e] = sc;
                if (e < 2) mx0 = fmaxf(mx0, sc); else mx1 = fmaxf(mx1, sc);
            }
        }
        mx0 = fmaxf(mx0, __shfl_xor_sync(0xffffffffu, mx0, 1));
        mx0 = fmaxf(mx0, __shfl_xor_sync(0xffffffffu, mx0, 2));
        mx1 = fmaxf(mx1, __shfl_xor_sync(0xffffffffu, mx1, 1));
        mx1 = fmaxf(mx1, __shfl_xor_sync(0xffffffffu, mx1, 2));

        float mn0 = fmaxf(m0, mx0);
        float mn1 = fmaxf(m1, mx1);
        float a0 = __expf(m0 - mn0);
        float a1 = __expf(m1 - mn1);
        m0 = mn0; m1 = mn1;
        l0 *= a0;  l1 *= a1;
#pragma unroll
        for (int nd = 0; nd < 8; nd++) {
            o[nd][0] *= a0; o[nd][1] *= a0;
            o[nd][2] *= a1; o[nd][3] *= a1;
        }

        // p = exp(s - m), split to hi/lo tf32
        uint32_t ph[4][4], pl[4][4];
#pragma unroll
        for (int nt = 0; nt < 4; nt++) {
#pragma unroll
            for (int e = 0; e < 4; e++) {
                float mm = (e < 2) ? mn0 : mn1;
                float p = __expf(s[nt][e] - mm);
                if (e < 2) l0 += p; else l1 += p;
                uint32_t hi = f2tf(p);
                ph[nt][e] = hi;
                pl[nt][e] = f2tf(p - __uint_as_float(hi));
            }
        }

        // PV: O += P * V   (3xTF32)
        const int srcA = 4 * g + (t >> 1);
        const int srcB = srcA + 2;
        const bool odd = (t & 1);
#pragma unroll
        for (int kt = 0; kt < 4; kt++) {
            uint32_t ah[4], al[4];
            {
                uint32_t x0 = __shfl_sync(0xffffffffu, ph[kt][0], srcA);
                uint32_t x1 = __shfl_sync(0xffffffffu, ph[kt][1], srcA);
                uint32_t x2 = __shfl_sync(0xffffffffu, ph[kt][2], srcA);
                uint32_t x3 = __shfl_sync(0xffffffffu, ph[kt][3], srcA);
                uint32_t y0 = __shfl_sync(0xffffffffu, ph[kt][0], srcB);
                uint32_t y1 = __shfl_sync(0xffffffffu, ph[kt][1], srcB);
                uint32_t y2 = __shfl_sync(0xffffffffu, ph[kt][2], srcB);
                uint32_t y3 = __shfl_sync(0xffffffffu, ph[kt][3], srcB);
                ah[0] = odd ? x1 : x0;
                ah[1] = odd ? x3 : x2;
                ah[2] = odd ? y1 : y0;
                ah[3] = odd ? y3 : y2;
            }
            {
                uint32_t x0 = __shfl_sync(0xffffffffu, pl[kt][0], srcA);
                uint32_t x1 = __shfl_sync(0xffffffffu, pl[kt][1], srcA);
                uint32_t x2 = __shfl_sync(0xffffffffu, pl[kt][2], srcA);
                uint32_t x3 = __shfl_sync(0xffffffffu, pl[kt][3], srcA);
                uint32_t y0 = __shfl_sync(0xffffffffu, pl[kt][0], srcB);
                uint32_t y1 = __shfl_sync(0xffffffffu, pl[kt][1], srcB);
                uint32_t y2 = __shfl_sync(0xffffffffu, pl[kt][2], srcB);
                uint32_t y3 = __shfl_sync(0xffffffffu, pl[kt][3], srcB);
                al[0] = odd ? x1 : x0;
                al[1] = odd ? x3 : x2;
                al[2] = odd ? y1 : y0;
                al[3] = odd ? y3 : y2;
            }
#pragma unroll
            for (int nd = 0; nd < 8; nd++) {
                uint32_t bh[2], bl[2];
                bh[0] = Vh[kt * 8 + t][nd * 8 + g];
                bh[1] = Vh[kt * 8 + t + 4][nd * 8 + g];
                bl[0] = Vl[kt * 8 + t][nd * 8 + g];
                bl[1] = Vl[kt * 8 + t + 4][nd * 8 + g];
                mma8(o[nd], ah, bh);
                mma8(o[nd], ah, bl);
                mma8(o[nd], al, bh);
            }
        }
        __syncthreads();
    }

    // finalize: row-sum reduce, normalize, store
    l0 += __shfl_xor_sync(0xffffffffu, l0, 1);
    l0 += __shfl_xor_sync(0xffffffffu, l0, 2);
    l1 += __shfl_xor_sync(0xffffffffu, l1, 1);
    l1 += __shfl_xor_sync(0xffffffffu, l1, 2);
    float inv0 = 1.f / l0;
    float inv1 = 1.f / l1;

#pragma unroll
    for (int nd = 0; nd < 8; nd++) {
        int col = h * HD + nd * 8 + 2 * t;
        *(float2*)(g_A + (size_t)r0 * 1024 + col) = make_float2(o[nd][0] * inv0, o[nd][1] * inv0);
        *(float2*)(g_A + (size_t)r1 * 1024 + col) = make_float2(o[nd][2] * inv1, o[nd][3] * inv1);
    }
}

// ---------------- launch -------------------------------------------------------
extern "C" void kernel_launch(void* const* d_in, const int* in_sizes, int n_in,
                              void* d_out, int out_size)
{
    const float* x  = (const float*)d_in[0];
    const float* Wq = (const float*)d_in[1];
    const float* Wk = (const float*)d_in[2];
    const float* Wv = (const float*)d_in[3];
    const float* Wo = (const float*)d_in[4];
    float* out = (float*)d_out;

    dim3 gQKV(DOUT / 128, SEQ / 128, 3);
    gemm_qkv_kernel<<<gQKV, 256>>>(x, Wq, Wk, Wv);

    dim3 gAtt(SEQ / 64, NHEAD);
    attn_kernel<<<gAtt, 128>>>();

    dim3 gOut(DOUT / 128, SEQ / 128, 1);
    gemm_wo_kernel<<<gOut, 256>>>(Wo, out);
}

// round 3
// speedup vs baseline: 1.9842x; 1.2629x over previous
#include <cuda_runtime.h>
#include <stdint.h>

#define SEQ 4096
#define DM  1024
#define NHEAD 16
#define HD 64

// ---------------- device scratch ----------------
__device__ uint32_t g_Xh[SEQ*DM], g_Xl[SEQ*DM];
__device__ uint32_t g_Wth[4*DM*DM], g_Wtl[4*DM*DM];   // transposed [n][k], tf32 hi/lo
__device__ uint32_t g_Qf[SEQ*DM], g_Kf[SEQ*DM];       // tf32 (Q pre-scaled by 0.125)
__device__ float    g_V[SEQ*DM];
__device__ uint32_t g_Vth[SEQ*DM], g_Vtl[SEQ*DM];     // V transposed: [c][j] = [c*SEQ + j]
__device__ uint32_t g_Ah[SEQ*DM], g_Al[SEQ*DM];       // attention out, pre-split

// ---------------- helpers ----------------
__device__ __forceinline__ uint32_t f2tf(float x){
    uint32_t r; asm("cvt.rna.tf32.f32 %0, %1;" : "=r"(r) : "f"(x)); return r;
}
__device__ __forceinline__ void split2(float v, uint32_t& h, uint32_t& l){
    h = f2tf(v); l = f2tf(v - __uint_as_float(h));
}
__device__ __forceinline__ void mma8(float* c, const uint32_t* a, const uint32_t* b){
    asm volatile(
        "mma.sync.aligned.m16n8k8.row.col.f32.tf32.tf32.f32 "
        "{%0,%1,%2,%3}, {%4,%5,%6,%7}, {%8,%9}, {%0,%1,%2,%3};"
        : "+f"(c[0]), "+f"(c[1]), "+f"(c[2]), "+f"(c[3])
        : "r"(a[0]), "r"(a[1]), "r"(a[2]), "r"(a[3]), "r"(b[0]), "r"(b[1]));
}
__device__ __forceinline__ void ldsm4(uint32_t* r, uint32_t addr){
    asm volatile("ldmatrix.sync.aligned.m8n8.x4.shared.b16 {%0,%1,%2,%3}, [%4];"
        : "=r"(r[0]), "=r"(r[1]), "=r"(r[2]), "=r"(r[3]) : "r"(addr));
}
__device__ __forceinline__ void cpa16(uint32_t dst, const void* src){
    asm volatile("cp.async.cg.shared.global [%0], [%1], 16;" :: "r"(dst), "l"(src));
}
#define CPCOMMIT asm volatile("cp.async.commit_group;")
template<int N> __device__ __forceinline__ void cpwait(){
    asm volatile("cp.async.wait_group %0;" :: "n"(N));
}

// ---------------- setup kernels ----------------
__global__ void split_x_kernel(const float* __restrict__ X){
    int i = (blockIdx.x * 256 + threadIdx.x) * 4;
    float4 v = *(const float4*)(X + i);
    uint32_t h, l;
    split2(v.x, h, l); g_Xh[i+0] = h; g_Xl[i+0] = l;
    split2(v.y, h, l); g_Xh[i+1] = h; g_Xl[i+1] = l;
    split2(v.z, h, l); g_Xh[i+2] = h; g_Xl[i+2] = l;
    split2(v.w, h, l); g_Xh[i+3] = h; g_Xl[i+3] = l;
}

// W [k][n] -> Wt [n][k] hi/lo, z selects which weight
__global__ void splitT_w_kernel(const float* __restrict__ W0, const float* __restrict__ W1,
                                const float* __restrict__ W2, const float* __restrict__ W3){
    __shared__ float tile[32][33];
    int z = blockIdx.z;
    const float* W = (z==0)?W0:(z==1)?W1:(z==2)?W2:W3;
    uint32_t* oh = g_Wth + (size_t)z * DM * DM;
    uint32_t* ol = g_Wtl + (size_t)z * DM * DM;
    int tx = threadIdx.x, ty = threadIdx.y;
    int x = blockIdx.x * 32 + tx, y = blockIdx.y * 32 + ty;
#pragma unroll
    for (int i = 0; i < 32; i += 8)
        tile[ty + i][tx] = W[(size_t)(y + i) * DM + x];
    __syncthreads();
    int xo = blockIdx.y * 32 + tx, yo = blockIdx.x * 32 + ty;
#pragma unroll
    for (int i = 0; i < 32; i += 8){
        float v = tile[tx][ty + i];
        uint32_t h, l; split2(v, h, l);
        oh[(size_t)(yo + i) * DM + xo] = h;
        ol[(size_t)(yo + i) * DM + xo] = l;
    }
}

// g_V [j][c] -> Vt [c][j] hi/lo
__global__ void vsplitT_kernel(){
    __shared__ float tile[32][33];
    int tx = threadIdx.x, ty = threadIdx.y;
    int x = blockIdx.x * 32 + tx, y = blockIdx.y * 32 + ty;
#pragma unroll
    for (int i = 0; i < 32; i += 8)
        tile[ty + i][tx] = g_V[(size_t)(y + i) * DM + x];
    __syncthreads();
    int c = blockIdx.x * 32 + ty, j = blockIdx.y * 32 + tx;
#pragma unroll
    for (int i = 0; i < 32; i += 8){
        float v = tile[tx][ty + i];
        uint32_t h, l; split2(v, h, l);
        g_Vth[(size_t)(c + i) * SEQ + j] = h;
        g_Vtl[(size_t)(c + i) * SEQ + j] = l;
    }
}

// ---------------- GEMM core (3xTF32, 128x128 tile, BK=16, 256 thr) ----------------
#define G_ABUF 2560                 // 128*20 words
#define G_OAH(b) ((b)*G_ABUF)
#define G_OAL(b) (5120 + (b)*G_ABUF)
#define G_OBH(b) (10240 + (b)*G_ABUF)
#define G_OBL(b) (15360 + (b)*G_ABUF)
#define G_SMEM_BYTES (20480*4)

__device__ __forceinline__ void gemm_core(const uint32_t* __restrict__ Agh,
                                          const uint32_t* __restrict__ Agl,
                                          const uint32_t* __restrict__ Bgh,
                                          const uint32_t* __restrict__ Bgl,
                                          uint32_t* sm, float acc[4][4][4])
{
    const int tid  = threadIdx.x;
    const int lane = tid & 31;
    const int w    = tid >> 5;
    const int wm   = w >> 2, wn = w & 3;
    const int bm   = blockIdx.y, bn = blockIdx.x;
    const uint32_t smb = (uint32_t)__cvta_generic_to_shared(sm);

#pragma unroll
    for (int i = 0; i < 4; i++)
#pragma unroll
        for (int j = 0; j < 4; j++)
#pragma unroll
            for (int e = 0; e < 4; e++) acc[i][j][e] = 0.f;

    // cp.async mapping: 2 chunks per array per thread
    const int cr0 = tid >> 2;            // rows 0..63
    const int cr1 = cr0 + 64;            // rows 64..127
    const int cc4 = (tid & 3) * 4;       // k word offset 0,4,8,12
    const int sw0 = cr0 * 20 + cc4;
    const int sw1 = cr1 * 20 + cc4;
    const size_t ga0 = (size_t)(bm * 128 + cr0) * DM + cc4;
    const size_t ga1 = (size_t)(bm * 128 + cr1) * DM + cc4;
    const size_t gb0 = (size_t)(bn * 128 + cr0) * DM + cc4;
    const size_t gb1 = (size_t)(bn * 128 + cr1) * DM + cc4;

    // ldmatrix address components
    const int lrow  = (lane & 7) + ((lane >> 3) & 1) * 8;
    const int lcA   = ((lane >> 4) & 1) * 4;
    const int lrowB = (lane & 7) + ((lane >> 4) & 1) * 8;
    const int lcB   = ((lane >> 3) & 1) * 4;
    int aoff[4], boff[2];
#pragma unroll
    for (int mt = 0; mt < 4; mt++) aoff[mt] = (wm*64 + mt*16 + lrow) * 20 + lcA;
#pragma unroll
    for (int np = 0; np < 2; np++) boff[np] = (wn*32 + np*16 + lrowB) * 20 + lcB;

    // prefetch tile 0
    {
        cpa16(smb + (G_OAH(0)+sw0)*4, Agh + ga0);
        cpa16(smb + (G_OAH(0)+sw1)*4, Agh + ga1);
        cpa16(smb + (G_OAL(0)+sw0)*4, Agl + ga0);
        cpa16(smb + (G_OAL(0)+sw1)*4, Agl + ga1);
        cpa16(smb + (G_OBH(0)+sw0)*4, Bgh + gb0);
        cpa16(smb + (G_OBH(0)+sw1)*4, Bgh + gb1);
        cpa16(smb + (G_OBL(0)+sw0)*4, Bgl + gb0);
        cpa16(smb + (G_OBL(0)+sw1)*4, Bgl + gb1);
        CPCOMMIT;
    }

    int buf = 0;
    for (int kt = 0; kt < 64; kt++){
        if (kt < 63){
            int nb = buf ^ 1, ko = (kt + 1) * 16;
            cpa16(smb + (G_OAH(nb)+sw0)*4, Agh + ga0 + ko);
            cpa16(smb + (G_OAH(nb)+sw1)*4, Agh + ga1 + ko);
            cpa16(smb + (G_OAL(nb)+sw0)*4, Agl + ga0 + ko);
            cpa16(smb + (G_OAL(nb)+sw1)*4, Agl + ga1 + ko);
            cpa16(smb + (G_OBH(nb)+sw0)*4, Bgh + gb0 + ko);
            cpa16(smb + (G_OBH(nb)+sw1)*4, Bgh + gb1 + ko);
            cpa16(smb + (G_OBL(nb)+sw0)*4, Bgl + gb0 + ko);
            cpa16(smb + (G_OBL(nb)+sw1)*4, Bgl + gb1 + ko);
            CPCOMMIT;
            cpwait<1>();
        } else {
            cpwait<0>();
        }
        __syncthreads();

        const int ah = G_OAH(buf), al = G_OAL(buf), bh = G_OBH(buf), bl = G_OBL(buf);
#pragma unroll
        for (int ks = 0; ks < 2; ks++){
            uint32_t Af[4][4], Alf[4][4], Bf[2][4], Blf[2][4];
#pragma unroll
            for (int mt = 0; mt < 4; mt++){
                ldsm4(Af[mt],  smb + (ah + aoff[mt] + ks*8)*4);
                ldsm4(Alf[mt], smb + (al + aoff[mt] + ks*8)*4);
            }
#pragma unroll
            for (int np = 0; np < 2; np++){
                ldsm4(Bf[np],  smb + (bh + boff[np] + ks*8)*4);
                ldsm4(Blf[np], smb + (bl + boff[np] + ks*8)*4);
            }
#pragma unroll
            for (int mt = 0; mt < 4; mt++)
#pragma unroll
                for (int nt = 0; nt < 4; nt++){
                    const uint32_t* bhp = &Bf [nt>>1][(nt&1)*2];
                    const uint32_t* blp = &Blf[nt>>1][(nt&1)*2];
                    mma8(acc[mt][nt], Af[mt],  bhp);
                    mma8(acc[mt][nt], Af[mt],  blp);
                    mma8(acc[mt][nt], Alf[mt], bhp);
                }
        }
        __syncthreads();
        buf ^= 1;
    }
}

extern __shared__ uint32_t dynsm[];

__global__ __launch_bounds__(256)
void gemm_qkv_kernel(){
    float acc[4][4][4];
    const int z = blockIdx.z;
    gemm_core(g_Xh, g_Xl, g_Wth + (size_t)z*DM*DM, g_Wtl + (size_t)z*DM*DM, dynsm, acc);

    const int tid = threadIdx.x, lane = tid & 31, w = tid >> 5;
    const int g = lane >> 2, t = lane & 3, wm = w >> 2, wn = w & 3;
#pragma unroll
    for (int mt = 0; mt < 4; mt++){
        int r = blockIdx.y*128 + wm*64 + mt*16 + g;
#pragma unroll
        for (int nt = 0; nt < 4; nt++){
            int c = blockIdx.x*128 + wn*32 + nt*8 + 2*t;
            float v0 = acc[mt][nt][0], v1 = acc[mt][nt][1];
            float v2 = acc[mt][nt][2], v3 = acc[mt][nt][3];
            if (z == 2){
                *(float2*)(g_V + (size_t)r*DM + c)     = make_float2(v0, v1);
                *(float2*)(g_V + (size_t)(r+8)*DM + c) = make_float2(v2, v3);
            } else {
                float sc = (z == 0) ? 0.125f : 1.0f;
                uint32_t* dst = (z == 0) ? g_Qf : g_Kf;
                *(uint2*)(dst + (size_t)r*DM + c)     = make_uint2(f2tf(v0*sc), f2tf(v1*sc));
                *(uint2*)(dst + (size_t)(r+8)*DM + c) = make_uint2(f2tf(v2*sc), f2tf(v3*sc));
            }
        }
    }
}

__global__ __launch_bounds__(256)
void gemm_wo_kernel(float* __restrict__ out){
    float acc[4][4][4];
    gemm_core(g_Ah, g_Al, g_Wth + (size_t)3*DM*DM, g_Wtl + (size_t)3*DM*DM, dynsm, acc);

    const int tid = threadIdx.x, lane = tid & 31, w = tid >> 5;
    const int g = lane >> 2, t = lane & 3, wm = w >> 2, wn = w & 3;
#pragma unroll
    for (int mt = 0; mt < 4; mt++){
        int r = blockIdx.y*128 + wm*64 + mt*16 + g;
#pragma unroll
        for (int nt = 0; nt < 4; nt++){
            int c = blockIdx.x*128 + wn*32 + nt*8 + 2*t;
            *(float2*)(out + (size_t)r*DM + c)     = make_float2(acc[mt][nt][0], acc[mt][nt][1]);
            *(float2*)(out + (size_t)(r+8)*DM + c) = make_float2(acc[mt][nt][2], acc[mt][nt][3]);
        }
    }
}

// ---------------- attention (q-tile 128, kv-tile 32, 8 warps) ----------------
#define A_KBUF 2176                   // 32*68
#define A_OK(b)  ((b)*A_KBUF)
#define A_VBUF 2304                   // 64*36
#define A_OVH(b) (4352 + (b)*A_VBUF)
#define A_OVL(b) (8960 + (b)*A_VBUF)
#define A_OPQ    13568
#define A_SMEM_BYTES (22784*4)

__global__ __launch_bounds__(256)
void attn_kernel(){
    uint32_t* sm = dynsm;
    const uint32_t smb = (uint32_t)__cvta_generic_to_shared(sm);
    const int tid = threadIdx.x, lane = tid & 31, w = tid >> 5;
    const int g = lane >> 2, t = lane & 3;
    const int h = blockIdx.y;
    const int q0 = blockIdx.x * 128;

    const int lrow  = (lane & 7) + ((lane >> 3) & 1) * 8;
    const int lcA   = ((lane >> 4) & 1) * 4;
    const int lrowB = (lane & 7) + ((lane >> 4) & 1) * 8;
    const int lcB   = ((lane >> 3) & 1) * 4;

    // cp.async mappings
    const int kr = tid >> 4, kc = (tid & 15) * 4;        // K: 2 chunks (rows kr, kr+16)
    const int vr = tid >> 3, vc = (tid & 7) * 4;         // V: 2 chunks (rows vr, vr+32)

    // prefetch KV tile 0 + Q, one group
    {
        cpa16(smb + (A_OK(0)  + kr*68 + kc)*4,      g_Kf  + (size_t)kr*DM + (size_t)h*64 + kc);
        cpa16(smb + (A_OK(0)  + (kr+16)*68 + kc)*4, g_Kf  + (size_t)(kr+16)*DM + (size_t)h*64 + kc);
        cpa16(smb + (A_OVH(0) + vr*36 + vc)*4,      g_Vth + (size_t)(h*64+vr)*SEQ + vc);
        cpa16(smb + (A_OVH(0) + (vr+32)*36 + vc)*4, g_Vth + (size_t)(h*64+vr+32)*SEQ + vc);
        cpa16(smb + (A_OVL(0) + vr*36 + vc)*4,      g_Vtl + (size_t)(h*64+vr)*SEQ + vc);
        cpa16(smb + (A_OVL(0) + (vr+32)*36 + vc)*4, g_Vtl + (size_t)(h*64+vr+32)*SEQ + vc);
#pragma unroll
        for (int i = 0; i < 8; i++){
            int c = tid + i*256;
            int qr = c >> 4, qc = (c & 15) * 4;
            cpa16(smb + (A_OPQ + qr*68 + qc)*4, g_Qf + (size_t)(q0+qr)*DM + (size_t)h*64 + qc);
        }
        CPCOMMIT;
    }
    cpwait<0>();
    __syncthreads();

    // extract Q fragments
    uint32_t qf[8][4];
#pragma unroll
    for (int kcc = 0; kcc < 8; kcc++)
        ldsm4(qf[kcc], smb + (A_OPQ + (w*16 + lrow)*68 + kcc*8 + lcA)*4);
    __syncthreads();      // Q region becomes P region

    float o[8][4];
#pragma unroll
    for (int nd = 0; nd < 8; nd++)
#pragma unroll
        for (int e = 0; e < 4; e++) o[nd][e] = 0.f;
    float m0 = -1e30f, m1 = -1e30f, l0 = 0.f, l1 = 0.f;

    const int r0 = q0 + w*16 + g, r1 = r0 + 8;
    const int ntile = blockIdx.x * 4 + 4;
    uint32_t* Ph = sm + A_OPQ + w * 1152;
    uint32_t* Pl = Ph + 576;
    const uint32_t phb = smb + (A_OPQ + w*1152)*4;
    const uint32_t plb = phb + 576*4;

    int buf = 0;
    for (int it = 0; it < ntile; it++){
        if (it + 1 < ntile){
            int nb = buf ^ 1, j1 = (it + 1) * 32;
            cpa16(smb + (A_OK(nb)  + kr*68 + kc)*4,      g_Kf  + (size_t)(j1+kr)*DM + (size_t)h*64 + kc);
            cpa16(smb + (A_OK(nb)  + (kr+16)*68 + kc)*4, g_Kf  + (size_t)(j1+kr+16)*DM + (size_t)h*64 + kc);
            cpa16(smb + (A_OVH(nb) + vr*36 + vc)*4,      g_Vth + (size_t)(h*64+vr)*SEQ + j1 + vc);
            cpa16(smb + (A_OVH(nb) + (vr+32)*36 + vc)*4, g_Vth + (size_t)(h*64+vr+32)*SEQ + j1 + vc);
            cpa16(smb + (A_OVL(nb) + vr*36 + vc)*4,      g_Vtl + (size_t)(h*64+vr)*SEQ + j1 + vc);
            cpa16(smb + (A_OVL(nb) + (vr+32)*36 + vc)*4, g_Vtl + (size_t)(h*64+vr+32)*SEQ + j1 + vc);
            CPCOMMIT;
            cpwait<1>();
        } else {
            cpwait<0>();
        }
        __syncthreads();

        // S = Q K^T
        float s[4][4];
#pragma unroll
        for (int nt = 0; nt < 4; nt++)
#pragma unroll
            for (int e = 0; e < 4; e++) s[nt][e] = 0.f;
#pragma unroll
        for (int kcc = 0; kcc < 8; kcc++){
            uint32_t Bf[2][4];
            ldsm4(Bf[0], smb + (A_OK(buf) + lrowB*68        + kcc*8 + lcB)*4);
            ldsm4(Bf[1], smb + (A_OK(buf) + (16+lrowB)*68   + kcc*8 + lcB)*4);
#pragma unroll
            for (int nt = 0; nt < 4; nt++)
                mma8(s[nt], qf[kcc], &Bf[nt>>1][(nt&1)*2]);
        }

        const int j0 = it * 32;
        const bool domask = (j0 >= q0);

        float mx0 = -1e30f, mx1 = -1e30f;
#pragma unroll
        for (int nt = 0; nt < 4; nt++){
            int jc = j0 + nt*8 + 2*t;
#pragma unroll
            for (int e = 0; e < 4; e++){
                int j = jc + (e & 1);
                int r = (e < 2) ? r0 : r1;
                float sc = s[nt][e];
                if (domask && j > r) sc = -1e30f;
                s[nt][e] = sc;
                if (e < 2) mx0 = fmaxf(mx0, sc); else mx1 = fmaxf(mx1, sc);
            }
        }
        mx0 = fmaxf(mx0, __shfl_xor_sync(0xffffffffu, mx0, 1));
        mx0 = fmaxf(mx0, __shfl_xor_sync(0xffffffffu, mx0, 2));
        mx1 = fmaxf(mx1, __shfl_xor_sync(0xffffffffu, mx1, 1));
        mx1 = fmaxf(mx1, __shfl_xor_sync(0xffffffffu, mx1, 2));

        float mn0 = fmaxf(m0, mx0), mn1 = fmaxf(m1, mx1);
        float a0 = __expf(m0 - mn0), a1 = __expf(m1 - mn1);
        m0 = mn0; m1 = mn1;
        l0 *= a0;  l1 *= a1;
#pragma unroll
        for (int nd = 0; nd < 8; nd++){
            o[nd][0] *= a0; o[nd][1] *= a0;
            o[nd][2] *= a1; o[nd][3] *= a1;
        }

        // p = exp(s-m), split, store to P smem (C-fragment layout)
#pragma unroll
        for (int nt = 0; nt < 4; nt++){
            float p0 = __expf(s[nt][0] - mn0), p1 = __expf(s[nt][1] - mn0);
            float p2 = __expf(s[nt][2] - mn1), p3 = __expf(s[nt][3] - mn1);
            l0 += p0 + p1; l1 += p2 + p3;
            uint32_t h0,lo0,h1,lo1,h2,lo2,h3,lo3;
            split2(p0,h0,lo0); split2(p1,h1,lo1);
            split2(p2,h2,lo2); split2(p3,h3,lo3);
            int col = nt*8 + 2*t;
            *(uint2*)(Ph + g*36 + col)     = make_uint2(h0, h1);
            *(uint2*)(Ph + (g+8)*36 + col) = make_uint2(h2, h3);
            *(uint2*)(Pl + g*36 + col)     = make_uint2(lo0, lo1);
            *(uint2*)(Pl + (g+8)*36 + col) = make_uint2(lo2, lo3);
        }
        __syncwarp();

        // O += P V
#pragma unroll
        for (int kt = 0; kt < 4; kt++){
            uint32_t pf[4], plf[4];
            ldsm4(pf,  phb + (lrow*36 + kt*8 + lcA)*4);
            ldsm4(plf, plb + (lrow*36 + kt*8 + lcA)*4);
#pragma unroll
            for (int np = 0; np < 4; np++){
                uint32_t Vf[4], Vlf[4];
                ldsm4(Vf,  smb + (A_OVH(buf) + (np*16+lrowB)*36 + kt*8 + lcB)*4);
                ldsm4(Vlf, smb + (A_OVL(buf) + (np*16+lrowB)*36 + kt*8 + lcB)*4);
                mma8(o[2*np],   pf,  &Vf[0]);
                mma8(o[2*np],   pf,  &Vlf[0]);
                mma8(o[2*np],   plf, &Vf[0]);
                mma8(o[2*np+1], pf,  &Vf[2]);
                mma8(o[2*np+1], pf,  &Vlf[2]);
                mma8(o[2*np+1], plf, &Vf[2]);
            }
        }
        __syncthreads();
        buf ^= 1;
    }

    l0 += __shfl_xor_sync(0xffffffffu, l0, 1);
    l0 += __shfl_xor_sync(0xffffffffu, l0, 2);
    l1 += __shfl_xor_sync(0xffffffffu, l1, 1);
    l1 += __shfl_xor_sync(0xffffffffu, l1, 2);
    float inv0 = 1.f / l0, inv1 = 1.f / l1;

#pragma unroll
    for (int nd = 0; nd < 8; nd++){
        int c = h*64 + nd*8 + 2*t;
        uint32_t h0,lo0,h1,lo1;
        split2(o[nd][0]*inv0, h0, lo0); split2(o[nd][1]*inv0, h1, lo1);
        *(uint2*)(g_Ah + (size_t)r0*DM + c) = make_uint2(h0, h1);
        *(uint2*)(g_Al + (size_t)r0*DM + c) = make_uint2(lo0, lo1);
        split2(o[nd][2]*inv1, h0, lo0); split2(o[nd][3]*inv1, h1, lo1);
        *(uint2*)(g_Ah + (size_t)r1*DM + c) = make_uint2(h0, h1);
        *(uint2*)(g_Al + (size_t)r1*DM + c) = make_uint2(lo0, lo1);
    }
}

// ---------------- launch ----------------
extern "C" void kernel_launch(void* const* d_in, const int* in_sizes, int n_in,
                              void* d_out, int out_size)
{
    const float* x  = (const float*)d_in[0];
    const float* Wq = (const float*)d_in[1];
    const float* Wk = (const float*)d_in[2];
    const float* Wv = (const float*)d_in[3];
    const float* Wo = (const float*)d_in[4];
    float* out = (float*)d_out;

    cudaFuncSetAttribute(gemm_qkv_kernel, cudaFuncAttributeMaxDynamicSharedMemorySize, G_SMEM_BYTES);
    cudaFuncSetAttribute(gemm_wo_kernel,  cudaFuncAttributeMaxDynamicSharedMemorySize, G_SMEM_BYTES);
    cudaFuncSetAttribute(attn_kernel,     cudaFuncAttributeMaxDynamicSharedMemorySize, A_SMEM_BYTES);

    split_x_kernel<<<SEQ*DM/1024, 256>>>(x);
    splitT_w_kernel<<<dim3(32,32,4), dim3(32,8)>>>(Wq, Wk, Wv, Wo);

    gemm_qkv_kernel<<<dim3(8,32,3), 256, G_SMEM_BYTES>>>();

    vsplitT_kernel<<<dim3(32,128), dim3(32,8)>>>();

    attn_kernel<<<dim3(32,16), 256, A_SMEM_BYTES>>>();

    gemm_wo_kernel<<<dim3(8,32), 256, G_SMEM_BYTES>>>(out);
}

// round 4
// speedup vs baseline: 3.1743x; 1.5998x over previous
#include <cuda_runtime.h>
#include <cuda_bf16.h>
#include <stdint.h>

#define SEQ 4096
#define DM  1024
#define NHEAD 16
#define HD 64

// ---------------- device scratch ----------------
__device__ uint16_t g_Xh[SEQ*DM], g_Xl[SEQ*DM];          // X bf16 hi/lo
__device__ uint16_t g_Wth[4*DM*DM], g_Wtl[4*DM*DM];      // W^T bf16 hi/lo [n][k]
__device__ uint32_t g_Qf[SEQ*DM], g_Kf[SEQ*DM];          // tf32 (Q pre-scaled 0.125)
__device__ float    g_V[SEQ*DM];
__device__ uint16_t g_Vth[SEQ*DM], g_Vtl[SEQ*DM];        // V^T bf16 hi/lo [c][j]
__device__ uint16_t g_Ah[SEQ*DM], g_Al[SEQ*DM];          // attn out bf16 hi/lo

// ---------------- helpers ----------------
__device__ __forceinline__ uint32_t f2tf(float x){
    uint32_t r; asm("cvt.rna.tf32.f32 %0, %1;" : "=r"(r) : "f"(x)); return r;
}
__device__ __forceinline__ void split2b(float v, uint16_t& h, uint16_t& l){
    __nv_bfloat16 bh = __float2bfloat16(v);
    h = __bfloat16_as_ushort(bh);
    l = __bfloat16_as_ushort(__float2bfloat16(v - __bfloat162float(bh)));
}
__device__ __forceinline__ void mma8(float* c, const uint32_t* a, const uint32_t* b){
    asm volatile(
        "mma.sync.aligned.m16n8k8.row.col.f32.tf32.tf32.f32 "
        "{%0,%1,%2,%3}, {%4,%5,%6,%7}, {%8,%9}, {%0,%1,%2,%3};"
        : "+f"(c[0]), "+f"(c[1]), "+f"(c[2]), "+f"(c[3])
        : "r"(a[0]), "r"(a[1]), "r"(a[2]), "r"(a[3]), "r"(b[0]), "r"(b[1]));
}
__device__ __forceinline__ void mma16(float* c, const uint32_t* a, const uint32_t* b){
    asm volatile(
        "mma.sync.aligned.m16n8k16.row.col.f32.bf16.bf16.f32 "
        "{%0,%1,%2,%3}, {%4,%5,%6,%7}, {%8,%9}, {%0,%1,%2,%3};"
        : "+f"(c[0]), "+f"(c[1]), "+f"(c[2]), "+f"(c[3])
        : "r"(a[0]), "r"(a[1]), "r"(a[2]), "r"(a[3]), "r"(b[0]), "r"(b[1]));
}
__device__ __forceinline__ void ldsm4(uint32_t* r, uint32_t addr){
    asm volatile("ldmatrix.sync.aligned.m8n8.x4.shared.b16 {%0,%1,%2,%3}, [%4];"
        : "=r"(r[0]), "=r"(r[1]), "=r"(r[2]), "=r"(r[3]) : "r"(addr));
}
__device__ __forceinline__ void cpa16(uint32_t dst, const void* src){
    asm volatile("cp.async.cg.shared.global [%0], [%1], 16;" :: "r"(dst), "l"(src));
}
#define CPCOMMIT asm volatile("cp.async.commit_group;")
template<int N> __device__ __forceinline__ void cpwait(){
    asm volatile("cp.async.wait_group %0;" :: "n"(N));
}

// ---------------- setup kernels ----------------
__global__ void split_x_kernel(const float* __restrict__ X){
    int i = (blockIdx.x * 256 + threadIdx.x) * 4;
    float4 v = *(const float4*)(X + i);
    uint16_t h0,l0,h1,l1,h2,l2,h3,l3;
    split2b(v.x,h0,l0); split2b(v.y,h1,l1); split2b(v.z,h2,l2); split2b(v.w,h3,l3);
    ((uint32_t*)g_Xh)[i/2]   = (uint32_t)h0 | ((uint32_t)h1 << 16);
    ((uint32_t*)g_Xh)[i/2+1] = (uint32_t)h2 | ((uint32_t)h3 << 16);
    ((uint32_t*)g_Xl)[i/2]   = (uint32_t)l0 | ((uint32_t)l1 << 16);
    ((uint32_t*)g_Xl)[i/2+1] = (uint32_t)l2 | ((uint32_t)l3 << 16);
}

__global__ void splitT_w_kernel(const float* __restrict__ W0, const float* __restrict__ W1,
                                const float* __restrict__ W2, const float* __restrict__ W3){
    __shared__ float tile[32][33];
    int z = blockIdx.z;
    const float* W = (z==0)?W0:(z==1)?W1:(z==2)?W2:W3;
    uint16_t* oh = g_Wth + (size_t)z * DM * DM;
    uint16_t* ol = g_Wtl + (size_t)z * DM * DM;
    int tx = threadIdx.x, ty = threadIdx.y;
    int x = blockIdx.x * 32 + tx, y = blockIdx.y * 32 + ty;
#pragma unroll
    for (int i = 0; i < 32; i += 8)
        tile[ty + i][tx] = W[(size_t)(y + i) * DM + x];
    __syncthreads();
    int xo = blockIdx.y * 32 + tx, yo = blockIdx.x * 32 + ty;
#pragma unroll
    for (int i = 0; i < 32; i += 8){
        float v = tile[tx][ty + i];
        uint16_t h, l; split2b(v, h, l);
        oh[(size_t)(yo + i) * DM + xo] = h;
        ol[(size_t)(yo + i) * DM + xo] = l;
    }
}

__global__ void vsplitT_kernel(){
    __shared__ float tile[32][33];
    int tx = threadIdx.x, ty = threadIdx.y;
    int x = blockIdx.x * 32 + tx, y = blockIdx.y * 32 + ty;
#pragma unroll
    for (int i = 0; i < 32; i += 8)
        tile[ty + i][tx] = g_V[(size_t)(y + i) * DM + x];
    __syncthreads();
    int c = blockIdx.x * 32 + ty, j = blockIdx.y * 32 + tx;
#pragma unroll
    for (int i = 0; i < 32; i += 8){
        float v = tile[tx][ty + i];
        uint16_t h, l; split2b(v, h, l);
        g_Vth[(size_t)(c + i) * SEQ + j] = h;
        g_Vtl[(size_t)(c + i) * SEQ + j] = l;
    }
}

// ---------------- bf16x3 GEMM core: 128x128 tile, BK=32, 256 thr -------------
// smem: [stage][array(Ah,Al,Bh,Bl)][128 rows][20 words]  (16 data + 4 pad)
#define G_ST   20
#define G_ARR  2560
#define G_OFF(s,a) (((s)*4 + (a)) * G_ARR)
#define G_SMEM_BYTES (2*4*G_ARR*4)

extern __shared__ uint32_t dynsm[];

__device__ __forceinline__ void gemm_core(const uint16_t* __restrict__ Agh,
                                          const uint16_t* __restrict__ Agl,
                                          const uint16_t* __restrict__ Bgh,
                                          const uint16_t* __restrict__ Bgl,
                                          float acc[4][4][4])
{
    const int tid  = threadIdx.x;
    const int lane = tid & 31;
    const int w    = tid >> 5;
    const int wm   = w >> 2, wn = w & 3;
    const int bm   = blockIdx.y, bn = blockIdx.x;
    const uint32_t smb = (uint32_t)__cvta_generic_to_shared(dynsm);

#pragma unroll
    for (int i = 0; i < 4; i++)
#pragma unroll
        for (int j = 0; j < 4; j++)
#pragma unroll
            for (int e = 0; e < 4; e++) acc[i][j][e] = 0.f;

    // cp.async mapping: 2 chunks (16B) per array per thread
    const int c0row = (2*tid) >> 2, c0off = (2*tid) & 3;
    const int c1row = (2*tid+1) >> 2, c1off = (2*tid+1) & 3;
    const size_t gA0 = (size_t)(bm*128 + c0row) * DM + c0off*8;
    const size_t gA1 = (size_t)(bm*128 + c1row) * DM + c1off*8;
    const size_t gB0 = (size_t)(bn*128 + c0row) * DM + c0off*8;
    const size_t gB1 = (size_t)(bn*128 + c1row) * DM + c1off*8;
    const int s0 = c0row*G_ST*4 + c0off*16;     // smem byte offsets within array
    const int s1 = c1row*G_ST*4 + c1off*16;

    // ldmatrix address components
    const int lrow  = (lane & 7) + ((lane >> 3) & 1) * 8;
    const int lcA   = ((lane >> 4) & 1) * 4;
    const int lrowB = (lane & 7) + ((lane >> 4) & 1) * 8;
    const int lcB   = ((lane >> 3) & 1) * 4;
    int aoff[4], boff[2];
#pragma unroll
    for (int mt = 0; mt < 4; mt++) aoff[mt] = (wm*64 + mt*16 + lrow) * G_ST + lcA;
#pragma unroll
    for (int np = 0; np < 2; np++) boff[np] = (wn*32 + np*16 + lrowB) * G_ST + lcB;

#define G_PREF(s, k0)                                                          \
    do {                                                                       \
        cpa16(smb + G_OFF(s,0)*4 + s0, Agh + gA0 + (k0));                      \
        cpa16(smb + G_OFF(s,0)*4 + s1, Agh + gA1 + (k0));                      \
        cpa16(smb + G_OFF(s,1)*4 + s0, Agl + gA0 + (k0));                      \
        cpa16(smb + G_OFF(s,1)*4 + s1, Agl + gA1 + (k0));                      \
        cpa16(smb + G_OFF(s,2)*4 + s0, Bgh + gB0 + (k0));                      \
        cpa16(smb + G_OFF(s,2)*4 + s1, Bgh + gB1 + (k0));                      \
        cpa16(smb + G_OFF(s,3)*4 + s0, Bgl + gB0 + (k0));                      \
        cpa16(smb + G_OFF(s,3)*4 + s1, Bgl + gB1 + (k0));                      \
        CPCOMMIT;                                                              \
    } while (0)

    G_PREF(0, 0);

    int buf = 0;
    for (int kt = 0; kt < 32; kt++){
        if (kt < 31){
            G_PREF(buf ^ 1, (kt + 1) * 32);
            cpwait<1>();
        } else {
            cpwait<0>();
        }
        __syncthreads();

        const int ah = G_OFF(buf,0), al = G_OFF(buf,1);
        const int bh = G_OFF(buf,2), bl = G_OFF(buf,3);
#pragma unroll
        for (int ks = 0; ks < 2; ks++){
            uint32_t Af[4][4], Alf[4][4], Bf[2][4], Blf[2][4];
#pragma unroll
            for (int mt = 0; mt < 4; mt++){
                ldsm4(Af[mt],  smb + (ah + aoff[mt] + ks*8)*4);
                ldsm4(Alf[mt], smb + (al + aoff[mt] + ks*8)*4);
            }
#pragma unroll
            for (int np = 0; np < 2; np++){
                ldsm4(Bf[np],  smb + (bh + boff[np] + ks*8)*4);
                ldsm4(Blf[np], smb + (bl + boff[np] + ks*8)*4);
            }
#pragma unroll
            for (int mt = 0; mt < 4; mt++)
#pragma unroll
                for (int nt = 0; nt < 4; nt++){
                    const uint32_t* bhp = &Bf [nt>>1][(nt&1)*2];
                    const uint32_t* blp = &Blf[nt>>1][(nt&1)*2];
                    mma16(acc[mt][nt], Af[mt],  bhp);
                    mma16(acc[mt][nt], Af[mt],  blp);
                    mma16(acc[mt][nt], Alf[mt], bhp);
                }
        }
        __syncthreads();
        buf ^= 1;
    }
#undef G_PREF
}

__global__ __launch_bounds__(256)
void gemm_qkv_kernel(){
    float acc[4][4][4];
    const int z = blockIdx.z;
    gemm_core(g_Xh, g_Xl, g_Wth + (size_t)z*DM*DM, g_Wtl + (size_t)z*DM*DM, acc);

    const int tid = threadIdx.x, lane = tid & 31, w = tid >> 5;
    const int g = lane >> 2, t = lane & 3, wm = w >> 2, wn = w & 3;
#pragma unroll
    for (int mt = 0; mt < 4; mt++){
        int r = blockIdx.y*128 + wm*64 + mt*16 + g;
#pragma unroll
        for (int nt = 0; nt < 4; nt++){
            int c = blockIdx.x*128 + wn*32 + nt*8 + 2*t;
            float v0 = acc[mt][nt][0], v1 = acc[mt][nt][1];
            float v2 = acc[mt][nt][2], v3 = acc[mt][nt][3];
            if (z == 2){
                *(float2*)(g_V + (size_t)r*DM + c)     = make_float2(v0, v1);
                *(float2*)(g_V + (size_t)(r+8)*DM + c) = make_float2(v2, v3);
            } else {
                float sc = (z == 0) ? 0.125f : 1.0f;
                uint32_t* dst = (z == 0) ? g_Qf : g_Kf;
                *(uint2*)(dst + (size_t)r*DM + c)     = make_uint2(f2tf(v0*sc), f2tf(v1*sc));
                *(uint2*)(dst + (size_t)(r+8)*DM + c) = make_uint2(f2tf(v2*sc), f2tf(v3*sc));
            }
        }
    }
}

__global__ __launch_bounds__(256)
void gemm_wo_kernel(float* __restrict__ out){
    float acc[4][4][4];
    gemm_core(g_Ah, g_Al, g_Wth + (size_t)3*DM*DM, g_Wtl + (size_t)3*DM*DM, acc);

    const int tid = threadIdx.x, lane = tid & 31, w = tid >> 5;
    const int g = lane >> 2, t = lane & 3, wm = w >> 2, wn = w & 3;
#pragma unroll
    for (int mt = 0; mt < 4; mt++){
        int r = blockIdx.y*128 + wm*64 + mt*16 + g;
#pragma unroll
        for (int nt = 0; nt < 4; nt++){
            int c = blockIdx.x*128 + wn*32 + nt*8 + 2*t;
            *(float2*)(out + (size_t)r*DM + c)     = make_float2(acc[mt][nt][0], acc[mt][nt][1]);
            *(float2*)(out + (size_t)(r+8)*DM + c) = make_float2(acc[mt][nt][2], acc[mt][nt][3]);
        }
    }
}

// ---------------- attention: QK tf32, PV bf16x3 ------------------------------
// K tile (tf32): 32 rows x 68 words, 2 buf.  V tile (bf16 h+l): 64 c-rows x 20 words, 2 buf.
// Q (tf32) 128 x 68; P (bf16 h+l) per warp 16 x 20 x 2 in the Q region.
#define A_KBUF 2176
#define A_OK(b)  ((b)*A_KBUF)
#define A_VBUF 2560                    // hi(1280)+lo(1280)
#define A_OVH(b) (4352 + (b)*A_VBUF)
#define A_OVL(b) (A_OVH(b) + 1280)
#define A_OPQ    9472
#define A_SMEM_BYTES ((A_OPQ + 128*68)*4)

__global__ __launch_bounds__(256)
void attn_kernel(){
    uint32_t* sm = dynsm;
    const uint32_t smb = (uint32_t)__cvta_generic_to_shared(sm);
    const int tid = threadIdx.x, lane = tid & 31, w = tid >> 5;
    const int g = lane >> 2, t = lane & 3;
    const int h = blockIdx.y;
    const int q0 = blockIdx.x * 128;

    const int lrow  = (lane & 7) + ((lane >> 3) & 1) * 8;
    const int lcA   = ((lane >> 4) & 1) * 4;
    const int lrowB = (lane & 7) + ((lane >> 4) & 1) * 8;
    const int lcB   = ((lane >> 3) & 1) * 4;

    // K cp.async: 2 chunks/thread (tf32)
    const int kr = tid >> 4, kc = (tid & 15) * 4;
    // V cp.async: row = tid>>2 (0..63), off = tid&3; one hi + one lo chunk each
    const int vrow = tid >> 2, voff = tid & 3;

#define A_PREF_KV(b, j0)                                                          \
    do {                                                                          \
        cpa16(smb + (A_OK(b) + kr*68 + kc)*4,      g_Kf + (size_t)((j0)+kr)*DM + (size_t)h*64 + kc);      \
        cpa16(smb + (A_OK(b) + (kr+16)*68 + kc)*4, g_Kf + (size_t)((j0)+kr+16)*DM + (size_t)h*64 + kc);   \
        cpa16(smb + (A_OVH(b)*4 + vrow*80 + voff*16), g_Vth + (size_t)(h*64+vrow)*SEQ + (j0) + voff*8);   \
        cpa16(smb + (A_OVL(b)*4 + vrow*80 + voff*16), g_Vtl + (size_t)(h*64+vrow)*SEQ + (j0) + voff*8);   \
        CPCOMMIT;                                                                 \
    } while (0)

    // prefetch tile 0 + Q
    A_PREF_KV(0, 0);
#pragma unroll
    for (int i = 0; i < 8; i++){
        int c = tid + i*256;
        int qr = c >> 4, qc = (c & 15) * 4;
        cpa16(smb + (A_OPQ + qr*68 + qc)*4, g_Qf + (size_t)(q0+qr)*DM + (size_t)h*64 + qc);
    }
    CPCOMMIT;
    cpwait<0>();
    __syncthreads();

    uint32_t qf[8][4];
#pragma unroll
    for (int kcc = 0; kcc < 8; kcc++)
        ldsm4(qf[kcc], smb + (A_OPQ + (w*16 + lrow)*68 + kcc*8 + lcA)*4);
    __syncthreads();       // Q region becomes P region

    float o[8][4];
#pragma unroll
    for (int nd = 0; nd < 8; nd++)
#pragma unroll
        for (int e = 0; e < 4; e++) o[nd][e] = 0.f;
    float m0 = -1e30f, m1 = -1e30f, l0 = 0.f, l1 = 0.f;

    const int r0 = q0 + w*16 + g, r1 = r0 + 8;
    const int ntile = blockIdx.x * 4 + 4;
    uint32_t* Ph = sm + A_OPQ + w * 640;
    uint32_t* Pl = Ph + 320;
    const uint32_t phb = smb + (A_OPQ + w*640)*4;
    const uint32_t plb = phb + 320*4;

    int buf = 0;
    for (int it = 0; it < ntile; it++){
        if (it + 1 < ntile){
            A_PREF_KV(buf ^ 1, (it + 1) * 32);
            cpwait<1>();
        } else {
            cpwait<0>();
        }
        __syncthreads();

        // S = Q K^T (tf32)
        float s[4][4];
#pragma unroll
        for (int nt = 0; nt < 4; nt++)
#pragma unroll
            for (int e = 0; e < 4; e++) s[nt][e] = 0.f;
#pragma unroll
        for (int kcc = 0; kcc < 8; kcc++){
            uint32_t Bf[2][4];
            ldsm4(Bf[0], smb + (A_OK(buf) + lrowB*68      + kcc*8 + lcB)*4);
            ldsm4(Bf[1], smb + (A_OK(buf) + (16+lrowB)*68 + kcc*8 + lcB)*4);
#pragma unroll
            for (int nt = 0; nt < 4; nt++)
                mma8(s[nt], qf[kcc], &Bf[nt>>1][(nt&1)*2]);
        }

        const int j0 = it * 32;
        const bool domask = (j0 >= q0);

        float mx0 = -1e30f, mx1 = -1e30f;
#pragma unroll
        for (int nt = 0; nt < 4; nt++){
            int jc = j0 + nt*8 + 2*t;
#pragma unroll
            for (int e = 0; e < 4; e++){
                int j = jc + (e & 1);
                int r = (e < 2) ? r0 : r1;
                float sc = s[nt][e];
                if (domask && j > r) sc = -1e30f;
                s[nt][e] = sc;
                if (e < 2) mx0 = fmaxf(mx0, sc); else mx1 = fmaxf(mx1, sc);
            }
        }
        mx0 = fmaxf(mx0, __shfl_xor_sync(0xffffffffu, mx0, 1));
        mx0 = fmaxf(mx0, __shfl_xor_sync(0xffffffffu, mx0, 2));
        mx1 = fmaxf(mx1, __shfl_xor_sync(0xffffffffu, mx1, 1));
        mx1 = fmaxf(mx1, __shfl_xor_sync(0xffffffffu, mx1, 2));

        float mn0 = fmaxf(m0, mx0), mn1 = fmaxf(m1, mx1);
        float a0 = __expf(m0 - mn0), a1 = __expf(m1 - mn1);
        m0 = mn0; m1 = mn1;
        l0 *= a0;  l1 *= a1;
#pragma unroll
        for (int nd = 0; nd < 8; nd++){
            o[nd][0] *= a0; o[nd][1] *= a0;
            o[nd][2] *= a1; o[nd][3] *= a1;
        }

        // p = exp(s-m), split to bf16 hi/lo, store packed pairs
#pragma unroll
        for (int nt = 0; nt < 4; nt++){
            float p0 = __expf(s[nt][0] - mn0), p1 = __expf(s[nt][1] - mn0);
            float p2 = __expf(s[nt][2] - mn1), p3 = __expf(s[nt][3] - mn1);
            l0 += p0 + p1; l1 += p2 + p3;
            uint16_t h0,lo0,h1,lo1,h2,lo2,h3,lo3;
            split2b(p0,h0,lo0); split2b(p1,h1,lo1);
            split2b(p2,h2,lo2); split2b(p3,h3,lo3);
            int pw = nt*4 + t;
            Ph[g*20 + pw]     = (uint32_t)h0  | ((uint32_t)h1  << 16);
            Ph[(g+8)*20 + pw] = (uint32_t)h2  | ((uint32_t)h3  << 16);
            Pl[g*20 + pw]     = (uint32_t)lo0 | ((uint32_t)lo1 << 16);
            Pl[(g+8)*20 + pw] = (uint32_t)lo2 | ((uint32_t)lo3 << 16);
        }
        __syncwarp();

        // O += P V  (bf16x3, k16)
#pragma unroll
        for (int kt = 0; kt < 2; kt++){
            uint32_t pf[4], plf[4];
            ldsm4(pf,  phb + (lrow*20 + kt*8 + lcA)*4);
            ldsm4(plf, plb + (lrow*20 + kt*8 + lcA)*4);
#pragma unroll
            for (int np = 0; np < 4; np++){
                uint32_t Vf[4], Vlf[4];
                ldsm4(Vf,  smb + (A_OVH(buf) + (np*16+lrowB)*20 + kt*8 + lcB)*4);
                ldsm4(Vlf, smb + (A_OVL(buf) + (np*16+lrowB)*20 + kt*8 + lcB)*4);
                mma16(o[2*np],   pf,  &Vf[0]);
                mma16(o[2*np],   pf,  &Vlf[0]);
                mma16(o[2*np],   plf, &Vf[0]);
                mma16(o[2*np+1], pf,  &Vf[2]);
                mma16(o[2*np+1], pf,  &Vlf[2]);
                mma16(o[2*np+1], plf, &Vf[2]);
            }
        }
        __syncthreads();
        buf ^= 1;
    }
#undef A_PREF_KV

    l0 += __shfl_xor_sync(0xffffffffu, l0, 1);
    l0 += __shfl_xor_sync(0xffffffffu, l0, 2);
    l1 += __shfl_xor_sync(0xffffffffu, l1, 1);
    l1 += __shfl_xor_sync(0xffffffffu, l1, 2);
    float inv0 = 1.f / l0, inv1 = 1.f / l1;

#pragma unroll
    for (int nd = 0; nd < 8; nd++){
        int c = h*64 + nd*8 + 2*t;
        uint16_t h0,lo0,h1,lo1;
        split2b(o[nd][0]*inv0, h0, lo0); split2b(o[nd][1]*inv0, h1, lo1);
        ((uint32_t*)g_Ah)[((size_t)r0*DM + c) >> 1] = (uint32_t)h0  | ((uint32_t)h1 << 16);
        ((uint32_t*)g_Al)[((size_t)r0*DM + c) >> 1] = (uint32_t)lo0 | ((uint32_t)lo1 << 16);
        split2b(o[nd][2]*inv1, h0, lo0); split2b(o[nd][3]*inv1, h1, lo1);
        ((uint32_t*)g_Ah)[((size_t)r1*DM + c) >> 1] = (uint32_t)h0  | ((uint32_t)h1 << 16);
        ((uint32_t*)g_Al)[((size_t)r1*DM + c) >> 1] = (uint32_t)lo0 | ((uint32_t)lo1 << 16);
    }
}

// ---------------- launch ----------------
extern "C" void kernel_launch(void* const* d_in, const int* in_sizes, int n_in,
                              void* d_out, int out_size)
{
    const float* x  = (const float*)d_in[0];
    const float* Wq = (const float*)d_in[1];
    const float* Wk = (const float*)d_in[2];
    const float* Wv = (const float*)d_in[3];
    const float* Wo = (const float*)d_in[4];
    float* out = (float*)d_out;

    cudaFuncSetAttribute(gemm_qkv_kernel, cudaFuncAttributeMaxDynamicSharedMemorySize, G_SMEM_BYTES);
    cudaFuncSetAttribute(gemm_wo_kernel,  cudaFuncAttributeMaxDynamicSharedMemorySize, G_SMEM_BYTES);
    cudaFuncSetAttribute(attn_kernel,     cudaFuncAttributeMaxDynamicSharedMemorySize, A_SMEM_BYTES);

    split_x_kernel<<<SEQ*DM/1024, 256>>>(x);
    splitT_w_kernel<<<dim3(32,32,4), dim3(32,8)>>>(Wq, Wk, Wv, Wo);

    gemm_qkv_kernel<<<dim3(8,32,3), 256, G_SMEM_BYTES>>>();

    vsplitT_kernel<<<dim3(32,128), dim3(32,8)>>>();

    attn_kernel<<<dim3(32,16), 256, A_SMEM_BYTES>>>();

    gemm_wo_kernel<<<dim3(8,32), 256, G_SMEM_BYTES>>>(out);
}